// round 3
// baseline (speedup 1.0000x reference)
#include <cuda_runtime.h>

#define BB 8
#define NN 1024
#define DD 128

typedef unsigned long long ull;

// ---------------- scratch (device globals; no allocation allowed) ----------
__device__ float g_v[BB * NN * DD];
__device__ float g_k[BB * NN * DD];
__device__ float g_q[BB * NN * DD];
__device__ float g_o[BB * NN * DD];
__device__ float g_kpe[NN * NN];
__device__ float g_vpe[NN * DD];

// ---------------- packed f32x2 helpers --------------------------------------
__device__ __forceinline__ void fma2(ull& d, ull a, ull b) {
    asm("fma.rn.f32x2 %0, %1, %2, %0;" : "+l"(d) : "l"(a), "l"(b));
}
__device__ __forceinline__ void add2(ull& d, ull a) {
    asm("add.rn.f32x2 %0, %0, %1;" : "+l"(d) : "l"(a));
}
__device__ __forceinline__ ull mul2(ull a, ull b) {
    ull d; asm("mul.rn.f32x2 %0, %1, %2;" : "=l"(d) : "l"(a), "l"(b)); return d;
}
__device__ __forceinline__ ull packf2(float lo, float hi) {
    ull d; asm("mov.b64 %0, {%1, %2};" : "=l"(d) : "f"(lo), "f"(hi)); return d;
}
__device__ __forceinline__ float2 unpackf2(ull v) {
    float2 f; asm("mov.b64 {%0, %1}, %2;" : "=f"(f.x), "=f"(f.y) : "l"(v)); return f;
}

// ---------------- kpe[n,m] = sum_d keys_pos_enc[n,m,d] ---------------------
__global__ void kpe_kernel(const float* __restrict__ kp) {
    int w = blockIdx.x * 8 + (threadIdx.x >> 5);
    int lane = threadIdx.x & 31;
    const float4* p = reinterpret_cast<const float4*>(kp) + (size_t)w * 32;
    float4 v = p[lane];
    float s = v.x + v.y + v.z + v.w;
#pragma unroll
    for (int o = 16; o >= 1; o >>= 1)
        s += __shfl_xor_sync(0xffffffffu, s, o);
    if (lane == 0) g_kpe[w] = s;
}

// ---------------- fused projection: v = X Wv^T; k = v Wk^T; q = v Wq^T -----
#define FPROJ_SMEM ((64 * 132 + 64 * 132 + 128 * 132) * 4)

__device__ __forceinline__ void gemm_64x128(const float* __restrict__ sA,
                                            const float* __restrict__ sWt,
                                            int ty, int tx, float acc[4][8]) {
#pragma unroll
    for (int i = 0; i < 4; i++)
#pragma unroll
        for (int j = 0; j < 8; j++) acc[i][j] = 0.f;
    for (int kk = 0; kk < 128; kk += 4) {
        float4 a[4];
#pragma unroll
        for (int i = 0; i < 4; i++)
            a[i] = *reinterpret_cast<const float4*>(sA + (ty * 4 + i) * 132 + kk);
#pragma unroll
        for (int t = 0; t < 4; t++) {
            float4 b0 = *reinterpret_cast<const float4*>(sWt + (kk + t) * 132 + tx * 8);
            float4 b1 = *reinterpret_cast<const float4*>(sWt + (kk + t) * 132 + tx * 8 + 4);
#pragma unroll
            for (int i = 0; i < 4; i++) {
                float aa = reinterpret_cast<const float*>(&a[i])[t];
                acc[i][0] += aa * b0.x; acc[i][1] += aa * b0.y;
                acc[i][2] += aa * b0.z; acc[i][3] += aa * b0.w;
                acc[i][4] += aa * b1.x; acc[i][5] += aa * b1.y;
                acc[i][6] += aa * b1.z; acc[i][7] += aa * b1.w;
            }
        }
    }
}

__device__ __forceinline__ void load_wt(const float* __restrict__ W,
                                        float* __restrict__ sWt, int tid) {
    for (int it = tid; it < 128 * 32; it += 256) {
        int o = it >> 5, e4 = it & 31;
        float4 v = *reinterpret_cast<const float4*>(W + o * DD + e4 * 4);
        sWt[(e4 * 4 + 0) * 132 + o] = v.x;
        sWt[(e4 * 4 + 1) * 132 + o] = v.y;
        sWt[(e4 * 4 + 2) * 132 + o] = v.z;
        sWt[(e4 * 4 + 3) * 132 + o] = v.w;
    }
}

__global__ __launch_bounds__(256) void proj_fused_kernel(
    const float* __restrict__ X, const float* __restrict__ Wv,
    const float* __restrict__ Wk, const float* __restrict__ Wq) {
    extern __shared__ float sm[];
    float* sX = sm;
    float* sV = sm + 64 * 132;
    float* sWt = sm + 2 * 64 * 132;

    int tid = threadIdx.x;
    int row0 = blockIdx.x * 64;
    int ty = tid >> 4, tx = tid & 15;
    float acc[4][8];

    for (int it = tid; it < 64 * 32; it += 256) {
        int r = it >> 5, c4 = it & 31;
        float4 v = *reinterpret_cast<const float4*>(X + (size_t)(row0 + r) * DD + c4 * 4);
        *reinterpret_cast<float4*>(sX + r * 132 + c4 * 4) = v;
    }
    load_wt(Wv, sWt, tid);
    __syncthreads();

    gemm_64x128(sX, sWt, ty, tx, acc);
    __syncthreads();
#pragma unroll
    for (int i = 0; i < 4; i++) {
        int r = ty * 4 + i;
        float4 lo = make_float4(acc[i][0], acc[i][1], acc[i][2], acc[i][3]);
        float4 hi = make_float4(acc[i][4], acc[i][5], acc[i][6], acc[i][7]);
        *reinterpret_cast<float4*>(sV + r * 132 + tx * 8) = lo;
        *reinterpret_cast<float4*>(sV + r * 132 + tx * 8 + 4) = hi;
        float* gp = g_v + (size_t)(row0 + r) * DD + tx * 8;
        *reinterpret_cast<float4*>(gp) = lo;
        *reinterpret_cast<float4*>(gp + 4) = hi;
    }
    load_wt(Wk, sWt, tid);
    __syncthreads();

    gemm_64x128(sV, sWt, ty, tx, acc);
#pragma unroll
    for (int i = 0; i < 4; i++) {
        float* gp = g_k + (size_t)(row0 + ty * 4 + i) * DD + tx * 8;
        *reinterpret_cast<float4*>(gp) = make_float4(acc[i][0], acc[i][1], acc[i][2], acc[i][3]);
        *reinterpret_cast<float4*>(gp + 4) = make_float4(acc[i][4], acc[i][5], acc[i][6], acc[i][7]);
    }
    __syncthreads();
    load_wt(Wq, sWt, tid);
    __syncthreads();

    gemm_64x128(sV, sWt, ty, tx, acc);
#pragma unroll
    for (int i = 0; i < 4; i++) {
        float* gp = g_q + (size_t)(row0 + ty * 4 + i) * DD + tx * 8;
        *reinterpret_cast<float4*>(gp) = make_float4(acc[i][0], acc[i][1], acc[i][2], acc[i][3]);
        *reinterpret_cast<float4*>(gp + 4) = make_float4(acc[i][4], acc[i][5], acc[i][6], acc[i][7]);
    }
}

// ---------------- fused attention (512 thr) + embedded vpe reduction -------
// block = (64-row tile, batch). Writes normalized O to g_o, vpe slice to g_vpe.
#define ATTN_SMEM ((64 * 132 + 64 * 128 + 64 * 128 + 64 * 68 + 64 + 64) * 4)
__global__ __launch_bounds__(512) void attn_kernel(
    const int* __restrict__ mask, const float* __restrict__ vpe_src) {
    extern __shared__ float sm[];
    float* sQ = sm;                     // 64 x 132
    float* sK = sQ + 64 * 132;          // 64 x 128, 16B-unit XOR swizzled
    float* sV = sK + 64 * 128;          // 64 x 128
    float* sP = sV + 64 * 128;          // 64 x 68
    float* sScale = sP + 64 * 68;       // 64
    float* sL = sScale + 64;            // 64

    int tid = threadIdx.x;
    int b = blockIdx.y;
    int n0 = blockIdx.x * 64;
    const float inv_s = 0.088388347648318447f;  // 1/sqrt(128)

    // Q tile, pre-scaled
    for (int it = tid; it < 64 * 32; it += 512) {
        int r = it >> 5, c4 = it & 31;
        float4 v = *reinterpret_cast<const float4*>(
            g_q + ((size_t)(b * NN + n0 + r)) * DD + c4 * 4);
        v.x *= inv_s; v.y *= inv_s; v.z *= inv_s; v.w *= inv_s;
        *reinterpret_cast<float4*>(sQ + r * 132 + c4 * 4) = v;
    }

    // S-GEMM mapping: rows ty*2+i (i<2), cols tx+16j (j<4)
    int ty = tid >> 4, tx = tid & 15;
    // O-GEMM mapping: rows oy*4+i (i<4), cols ox*4..ox*4+3
    int oy = tid >> 5, ox = tid & 31;

    // vpe slice: this block owns rows [vbid*8, vbid*8+8)
    int vbid = blockIdx.y * gridDim.x + blockIdx.x;   // 0..127
    int vn = vbid * 8 + (tid >> 6);                   // row in [0,1024)
    int vd2 = tid & 63;                               // float2 column
    const ull* vp2 = reinterpret_cast<const ull*>(vpe_src) + (size_t)vn * NN * 64 + vd2;
    ull vacc[4] = {0ull, 0ull, 0ull, 0ull};

    float m_run[2], l_run[2];
#pragma unroll
    for (int i = 0; i < 2; i++) { m_run[i] = -1e30f; l_run[i] = 0.f; }
    ull accd[4][2];
#pragma unroll
    for (int i = 0; i < 4; i++) { accd[i][0] = 0ull; accd[i][1] = 0ull; }

    for (int t = 0; t < 16; t++) {
        int m0 = t * 64;
        __syncthreads();  // prior tile's reads of sK/sV/sP complete
        for (int it = tid; it < 64 * 32; it += 512) {
            int r = it >> 5, c4 = it & 31;
            size_t gro = ((size_t)(b * NN + m0 + r)) * DD + c4 * 4;
            float4 kv = *reinterpret_cast<const float4*>(g_k + gro);
            *reinterpret_cast<float4*>(sK + r * 128 + ((c4 ^ (r & 7)) * 4)) = kv;
            float4 vv = *reinterpret_cast<const float4*>(g_v + gro);
            *reinterpret_cast<float4*>(sV + r * 128 + c4 * 4) = vv;
        }
        // embedded vpe chunk: 64 m-values, packed adds, MLP via 4 partials
        {
            const ull* p = vp2 + (size_t)m0 * 64;
#pragma unroll 4
            for (int u = 0; u < 64; u += 4) {
                ull x0 = p[(u + 0) * 64];
                ull x1 = p[(u + 1) * 64];
                ull x2 = p[(u + 2) * 64];
                ull x3 = p[(u + 3) * 64];
                add2(vacc[0], x0); add2(vacc[1], x1);
                add2(vacc[2], x2); add2(vacc[3], x3);
            }
        }
        __syncthreads();

        // S = Q K^T (packed over k)
        ull acc2[2][4];
#pragma unroll
        for (int i = 0; i < 2; i++)
#pragma unroll
            for (int j = 0; j < 4; j++) acc2[i][j] = 0ull;

        for (int kk = 0; kk < 128; kk += 4) {
            int kkv = kk >> 2;
            ull a0[2], a1[2];
#pragma unroll
            for (int i = 0; i < 2; i++) {
                const ull* ap = reinterpret_cast<const ull*>(sQ + (ty * 2 + i) * 132 + kk);
                a0[i] = ap[0]; a1[i] = ap[1];
            }
#pragma unroll
            for (int j = 0; j < 4; j++) {
                int col = tx + 16 * j;
                const ull* bp = reinterpret_cast<const ull*>(
                    sK + col * 128 + ((kkv ^ (col & 7)) * 4));
                ull b0 = bp[0], b1 = bp[1];
                fma2(acc2[0][j], a0[0], b0); fma2(acc2[0][j], a1[0], b1);
                fma2(acc2[1][j], a0[1], b0); fma2(acc2[1][j], a1[1], b1);
            }
        }

        // + kpe*inv_s, mask, online softmax
#pragma unroll
        for (int i = 0; i < 2; i++) {
            int n = n0 + ty * 2 + i;
            const float* kpe_row = g_kpe + (size_t)n * NN + m0;
            const int* mrow = mask + ((size_t)b * NN + n) * NN + m0;
            float sv[4];
            float mx = -1e30f;
#pragma unroll
            for (int j = 0; j < 4; j++) {
                int c = tx + j * 16;
                float2 pr = unpackf2(acc2[i][j]);
                float e = pr.x + pr.y + kpe_row[c] * inv_s;
                e = (mrow[c] != 0) ? e : -1e30f;
                sv[j] = e;
                mx = fmaxf(mx, e);
            }
#pragma unroll
            for (int o = 8; o >= 1; o >>= 1)
                mx = fmaxf(mx, __shfl_xor_sync(0xffffffffu, mx, o));
            float mn = fmaxf(m_run[i], mx);
            float f = __expf(m_run[i] - mn);
            float rs = 0.f;
#pragma unroll
            for (int j = 0; j < 4; j++) {
                float p = (sv[j] < -5e29f) ? 0.f : __expf(sv[j] - mn);
                sP[(ty * 2 + i) * 68 + tx + j * 16] = p;
                rs += p;
            }
#pragma unroll
            for (int o = 8; o >= 1; o >>= 1)
                rs += __shfl_xor_sync(0xffffffffu, rs, o);
            l_run[i] = l_run[i] * f + rs;
            m_run[i] = mn;
            if (tx == 0) sScale[ty * 2 + i] = f;
        }
        __syncthreads();

        // O = diag(f) O + P V (packed over d)
#pragma unroll
        for (int i = 0; i < 4; i++) {
            float f = sScale[oy * 4 + i];
            ull ff = packf2(f, f);
            accd[i][0] = mul2(accd[i][0], ff);
            accd[i][1] = mul2(accd[i][1], ff);
        }
        for (int m = 0; m < 64; m += 4) {
            float4 a4[4];
#pragma unroll
            for (int i = 0; i < 4; i++)
                a4[i] = *reinterpret_cast<const float4*>(sP + (oy * 4 + i) * 68 + m);
#pragma unroll
            for (int mt = 0; mt < 4; mt++) {
                const ull* bp = reinterpret_cast<const ull*>(sV + (m + mt) * 128 + ox * 4);
                ull b0 = bp[0], b1 = bp[1];
#pragma unroll
                for (int i = 0; i < 4; i++) {
                    float p = reinterpret_cast<const float*>(&a4[i])[mt];
                    ull pp = packf2(p, p);
                    fma2(accd[i][0], pp, b0);
                    fma2(accd[i][1], pp, b1);
                }
            }
        }
    }

    // publish l, write normalized O
    if (tx == 0) {
#pragma unroll
        for (int i = 0; i < 2; i++) sL[ty * 2 + i] = l_run[i];
    }
    // write vpe slice
    {
        add2(vacc[0], vacc[1]); add2(vacc[2], vacc[3]); add2(vacc[0], vacc[2]);
        float2 r = unpackf2(vacc[0]);
        *reinterpret_cast<float2*>(g_vpe + vn * DD + vd2 * 2) = r;
    }
    __syncthreads();
#pragma unroll
    for (int i = 0; i < 4; i++) {
        int r = oy * 4 + i;
        float il = 1.0f / sL[r];
        float2 lo = unpackf2(accd[i][0]);
        float2 hi = unpackf2(accd[i][1]);
        float4 ov = make_float4(lo.x * il, lo.y * il, hi.x * il, hi.y * il);
        *reinterpret_cast<float4*>(g_o + ((size_t)(b * NN + n0 + r)) * DD + ox * 4) = ov;
    }
}

// ---------------- epilogue: out = LN(O + vpe) + v ---------------------------
__global__ __launch_bounds__(256) void epi_kernel(
    const float* __restrict__ gamma, const float* __restrict__ beta,
    float* __restrict__ out) {
    int tid = threadIdx.x;
    int b = blockIdx.y;
    int n = blockIdx.x * 64 + (tid >> 2);
    int part = tid & 3;

    const float* orow = g_o + ((size_t)(b * NN + n)) * DD;
    const float* vper = g_vpe + n * DD;
    float x[32];
    float sum = 0.f, sq = 0.f;
#pragma unroll
    for (int u = 0; u < 32; u += 4) {
        int d = part * 32 + u;
        float4 o4 = *reinterpret_cast<const float4*>(orow + d);
        float4 p4 = *reinterpret_cast<const float4*>(vper + d);
        float4 v;
        v.x = o4.x + p4.x; v.y = o4.y + p4.y;
        v.z = o4.z + p4.z; v.w = o4.w + p4.w;
        x[u] = v.x; x[u + 1] = v.y; x[u + 2] = v.z; x[u + 3] = v.w;
        sum += v.x + v.y + v.z + v.w;
        sq += v.x * v.x + v.y * v.y + v.z * v.z + v.w * v.w;
    }
#pragma unroll
    for (int o = 1; o <= 2; o <<= 1) {
        sum += __shfl_xor_sync(0xffffffffu, sum, o);
        sq += __shfl_xor_sync(0xffffffffu, sq, o);
    }
    float mu = sum * (1.f / 128.f);
    float var = sq * (1.f / 128.f) - mu * mu;
    float rstd = rsqrtf(var + 1e-5f);
    const float* gvr = g_v + ((size_t)(b * NN + n)) * DD;
    float* orow_out = out + ((size_t)(b * NN + n)) * DD;
#pragma unroll
    for (int u = 0; u < 32; u += 4) {
        int d = part * 32 + u;
        float4 gm = *reinterpret_cast<const float4*>(gamma + d);
        float4 bt = *reinterpret_cast<const float4*>(beta + d);
        float4 vv = *reinterpret_cast<const float4*>(gvr + d);
        float4 r4;
        r4.x = (x[u] - mu) * rstd * gm.x + bt.x + vv.x;
        r4.y = (x[u + 1] - mu) * rstd * gm.y + bt.y + vv.y;
        r4.z = (x[u + 2] - mu) * rstd * gm.z + bt.z + vv.z;
        r4.w = (x[u + 3] - mu) * rstd * gm.w + bt.w + vv.w;
        *reinterpret_cast<float4*>(orow_out + d) = r4;
    }
}

// ---------------- launch ---------------------------------------------------
extern "C" void kernel_launch(void* const* d_in, const int* in_sizes, int n_in,
                              void* d_out, int out_size) {
    const float* values = (const float*)d_in[0];
    const int* mask = (const int*)d_in[3];
    const float* vpe = (const float*)d_in[4];
    const float* kpe = (const float*)d_in[5];
    const float* Wv = (const float*)d_in[6];
    const float* Wk = (const float*)d_in[7];
    const float* Wq = (const float*)d_in[8];
    const float* ln_gamma = (const float*)d_in[9];
    const float* ln_beta = (const float*)d_in[10];
    float* out = (float*)d_out;

    static cudaStream_t s2 = nullptr;
    static cudaEvent_t ev_fork = nullptr, ev_kpe = nullptr;
    if (!s2) {
        cudaStreamCreateWithFlags(&s2, cudaStreamNonBlocking);
        cudaEventCreateWithFlags(&ev_fork, cudaEventDisableTiming);
        cudaEventCreateWithFlags(&ev_kpe, cudaEventDisableTiming);
        cudaFuncSetAttribute(proj_fused_kernel,
                             cudaFuncAttributeMaxDynamicSharedMemorySize, FPROJ_SMEM);
        cudaFuncSetAttribute(attn_kernel,
                             cudaFuncAttributeMaxDynamicSharedMemorySize, ATTN_SMEM);
    }

    // fork: kpe (HBM stream) on s2, projections (compute) on s0
    cudaEventRecord(ev_fork, 0);
    cudaStreamWaitEvent(s2, ev_fork, 0);
    kpe_kernel<<<NN * NN / 8, 256, 0, s2>>>(kpe);
    proj_fused_kernel<<<BB * NN / 64, 256, FPROJ_SMEM>>>(values, Wv, Wk, Wq);
    cudaEventRecord(ev_kpe, s2);
    cudaStreamWaitEvent(0, ev_kpe, 0);
    // attention (with embedded vpe reduction), then LN epilogue
    attn_kernel<<<dim3(NN / 64, BB), 512, ATTN_SMEM>>>(mask, vpe);
    epi_kernel<<<dim3(NN / 64, BB), 256>>>(ln_gamma, ln_beta, out);
}